// round 1
// baseline (speedup 1.0000x reference)
#include <cuda_runtime.h>

// Problem constants (fixed by the reference)
#define BB   4
#define CC   32
#define HH   64
#define WW   64
#define KK   64
#define HWV  (HH*WW)      // 4096
#define BCV  (BB*CC)      // 128
#define CAP  1024         // max support pixels per RF (analysis: <= ~960)
#define OHH  32
#define OWW  32

// ---------------- static device scratch (no allocation allowed) -------------
__device__ int   g_cnt[KK];                 // support size per k
__device__ int   g_pk_idx[KK*CAP];          // per-k support pixel indices
__device__ float g_pk_rf [KK*CAP];          // per-k support rf values
__device__ int   g_posmap[KK*HWV];          // pixel -> position within k's list
__device__ int   g_px_cnt[HWV];             // per-pixel active-k count
__device__ int   g_px_flat[HWV*KK];         // per-pixel flat indices k*CAP+pos
__device__ float g_ebuf[BCV*KK*CAP];        // scaled e = exp(u*rf)/denom  (32 MB)

// ---------------- P1: build per-k compact support lists (deterministic) -----
__global__ __launch_bounds__(256) void build_k_lists(const float* __restrict__ rfs) {
    const int k    = blockIdx.x;
    const int tid  = threadIdx.x;
    const int lane = tid & 31;
    const int wid  = tid >> 5;
    __shared__ int base;
    __shared__ int wcnt[8];
    if (tid == 0) base = 0;
    __syncthreads();
    for (int start = 0; start < HWV; start += 256) {
        const int p  = start + tid;
        const float rf = rfs[k*HWV + p];
        const bool act = (rf != 0.0f);
        const unsigned bal = __ballot_sync(0xffffffffu, act);
        if (lane == 0) wcnt[wid] = __popc(bal);
        __syncthreads();
        int woff = 0;
        #pragma unroll
        for (int w = 0; w < 8; w++) if (w < wid) woff += wcnt[w];
        const int pos = base + woff + __popc(bal & ((1u << lane) - 1u));
        if (act && pos < CAP) {
            g_pk_idx[k*CAP + pos] = p;
            g_pk_rf [k*CAP + pos] = rf;
            g_posmap[k*HWV + p]   = pos;
        }
        __syncthreads();
        if (tid == 0) {
            int t = 0;
            #pragma unroll
            for (int w = 0; w < 8; w++) t += wcnt[w];
            base += t;
        }
        __syncthreads();
    }
    if (tid == 0) g_cnt[k] = (base < CAP) ? base : CAP;
}

// ---------------- P2: build per-pixel transposed gather lists ---------------
__global__ __launch_bounds__(256) void build_px_lists(const float* __restrict__ rfs) {
    const int p = blockIdx.x * 256 + threadIdx.x;
    if (p >= HWV) return;
    int c = 0;
    #pragma unroll 4
    for (int k = 0; k < KK; k++) {
        const float rf = rfs[k*HWV + p];
        if (rf != 0.0f) {
            g_px_flat[p*KK + c] = k*CAP + g_posmap[k*HWV + p];
            c++;
        }
    }
    g_px_cnt[p] = c;
}

// ---------------- K1: per-(bc,k) masked softmax, single exp pass ------------
// exp(v - m) / (exp(-m) + sum exp(v - m))  ==  exp(v) / (1 + sum exp(v))
// (exact algebraic identity; no overflow: v <= ~5 here)
__global__ __launch_bounds__(128) void rf_softmax(const float* __restrict__ u) {
    const int k   = blockIdx.x;
    const int bc  = blockIdx.y;
    const int tid = threadIdx.x;
    const int n   = g_cnt[k];
    const float* __restrict__ up = u + bc*HWV;

    __shared__ float eb[CAP];
    __shared__ float wsum[4];
    __shared__ float sinv;

    float lsum = 0.0f;
    for (int i = tid; i < n; i += 128) {
        const float e = __expf(up[g_pk_idx[k*CAP + i]] * g_pk_rf[k*CAP + i]);
        eb[i] = e;
        lsum += e;
    }
    #pragma unroll
    for (int o = 16; o > 0; o >>= 1) lsum += __shfl_down_sync(0xffffffffu, lsum, o);
    if ((tid & 31) == 0) wsum[tid >> 5] = lsum;
    __syncthreads();
    if (tid == 0) sinv = 1.0f / (1.0f + (wsum[0] + wsum[1] + wsum[2] + wsum[3]));
    __syncthreads();
    const float inv = sinv;

    float* __restrict__ dst = g_ebuf + (bc*KK + k)*CAP;
    for (int i = tid; i < n; i += 128) dst[i] = eb[i] * inv;
}

// ---------------- K2: per-pixel gather over active RFs + 2x2 max pool -------
__global__ __launch_bounds__(1024) void gather_pool(float* __restrict__ out) {
    const int bc = blockIdx.x;
    const int t  = threadIdx.x;          // 1024 threads = 32x32 outputs
    const int oh = t >> 5;
    const int ow = t & 31;
    const float* __restrict__ Ebc = g_ebuf + bc*KK*CAP;

    float best = 0.0f;                   // h >= 0 always (matches reference)
    #pragma unroll
    for (int dy = 0; dy < 2; dy++) {
        #pragma unroll
        for (int dx = 0; dx < 2; dx++) {
            const int p = (2*oh + dy)*WW + (2*ow + dx);
            const int n = g_px_cnt[p];
            const int* __restrict__ fl = g_px_flat + p*KK;
            float s = 0.0f;
            for (int j = 0; j < n; j++) s += Ebc[fl[j]];
            best = fmaxf(best, s);
        }
    }
    out[bc*(OHH*OWW) + t] = best;
}

// ---------------- launch ------------------------------------------------------
extern "C" void kernel_launch(void* const* d_in, const int* in_sizes, int n_in,
                              void* d_out, int out_size) {
    const float* u   = (const float*)d_in[0];   // (4,32,64,64)
    const float* rfs = (const float*)d_in[1];   // (64,64,64)
    float* out = (float*)d_out;                 // (4,32,32,32)

    build_k_lists <<<KK, 256>>>(rfs);
    build_px_lists<<<(HWV + 255)/256, 256>>>(rfs);
    rf_softmax    <<<dim3(KK, BCV), 128>>>(u);
    gather_pool   <<<BCV, 1024>>>(out);
}

// round 2
// speedup vs baseline: 2.0294x; 2.0294x over previous
#include <cuda_runtime.h>

// Problem constants (fixed by the reference)
#define BB   4
#define CC   32
#define HH   64
#define WW   64
#define KK   64
#define HWV  (HH*WW)      // 4096
#define BCV  (BB*CC)      // 128
#define CAP  1024         // max support pixels per RF (analysis: <= ~960)
#define NG   4            // k-groups (partial-h accumulators)
#define NT   512          // threads per fused block
#define OHH  32
#define OWW  32

// ---------------- static device scratch (no allocation allowed) -------------
__device__ int   g_cnt[KK];          // support size per k
__device__ int2  g_pk[KK*CAP];       // packed {pixel, bits(rf * log2(e))}
__device__ float g_hpart[NG*BCV*HWV];// partial h sums per k-group (8 MB)

__device__ __forceinline__ float ex2_fast(float y) {
    float r;
    asm("ex2.approx.f32 %0, %1;" : "=f"(r) : "f"(y));
    return r;
}

// ---------------- P1: build per-k compact support lists (deterministic) -----
__global__ __launch_bounds__(256) void build_k_lists(const float* __restrict__ rfs) {
    const int k    = blockIdx.x;
    const int tid  = threadIdx.x;
    const int lane = tid & 31;
    const int wid  = tid >> 5;
    __shared__ int base;
    __shared__ int wcnt[8];
    if (tid == 0) base = 0;
    __syncthreads();
    const float LOG2E = 1.4426950408889634f;
    for (int start = 0; start < HWV; start += 256) {
        const int p  = start + tid;
        const float rf = rfs[k*HWV + p];
        const bool act = (rf != 0.0f);
        const unsigned bal = __ballot_sync(0xffffffffu, act);
        if (lane == 0) wcnt[wid] = __popc(bal);
        __syncthreads();
        int woff = 0;
        #pragma unroll
        for (int w = 0; w < 8; w++) if (w < wid) woff += wcnt[w];
        const int pos = base + woff + __popc(bal & ((1u << lane) - 1u));
        if (act && pos < CAP) {
            int2 v;
            v.x = p;
            v.y = __float_as_int(rf * LOG2E);
            g_pk[k*CAP + pos] = v;
        }
        __syncthreads();
        if (tid == 0) {
            int t = 0;
            #pragma unroll
            for (int w = 0; w < 8; w++) t += wcnt[w];
            base += t;
        }
        __syncthreads();
    }
    if (tid == 0) g_cnt[k] = (base < CAP) ? base : CAP;
}

// ---------------- K1: fused masked softmax + h accumulation -----------------
// exp(v - m) / (exp(-m) + sum exp(v - m)) == exp(v) / (1 + sum exp(v))
// Within one k all support pixels are distinct -> plain smem RMW is race-free;
// the reduction barriers order successive k's RMW passes. Fully deterministic.
__global__ __launch_bounds__(NT) void rf_fused(const float* __restrict__ u) {
    const int bc  = blockIdx.x;
    const int g   = blockIdx.y;
    const int tid = threadIdx.x;

    __shared__ float us[HWV];   // input tile (16 KB)
    __shared__ float hs[HWV];   // partial h accumulator (16 KB)
    __shared__ float wred[16];
    __shared__ float sinv;

    const float* __restrict__ up = u + bc*HWV;
    #pragma unroll
    for (int i = tid; i < HWV; i += NT) { us[i] = up[i]; hs[i] = 0.0f; }
    __syncthreads();

    // strided k assignment: group g handles k = g, g+NG, g+2*NG, ... (balance)
    for (int kk = 0; kk < KK/NG; kk++) {
        const int k = g + kk*NG;
        const int n = g_cnt[k];
        const int2* __restrict__ pr = g_pk + k*CAP;

        // up to CAP=1024 = 2*NT elements -> at most 2 per thread, in registers
        const int i0 = tid, i1 = tid + NT;
        int   p0 = 0, p1 = 0;
        float e0 = 0.0f, e1 = 0.0f;
        if (i0 < n) { int2 v = pr[i0]; p0 = v.x; e0 = ex2_fast(us[p0] * __int_as_float(v.y)); }
        if (i1 < n) { int2 v = pr[i1]; p1 = v.x; e1 = ex2_fast(us[p1] * __int_as_float(v.y)); }

        float lsum = e0 + e1;
        #pragma unroll
        for (int o = 16; o > 0; o >>= 1) lsum += __shfl_down_sync(0xffffffffu, lsum, o);
        if ((tid & 31) == 0) wred[tid >> 5] = lsum;
        __syncthreads();
        if (tid < 32) {
            float s = (tid < 16) ? wred[tid] : 0.0f;
            #pragma unroll
            for (int o = 8; o > 0; o >>= 1) s += __shfl_down_sync(0xffffffffu, s, o);
            if (tid == 0) sinv = 1.0f / (1.0f + s);
        }
        __syncthreads();
        const float inv = sinv;

        if (i0 < n) hs[p0] += e0 * inv;
        if (i1 < n) hs[p1] += e1 * inv;
        // next iteration's first __syncthreads orders these RMWs vs k+1's
    }
    __syncthreads();

    float* __restrict__ dst = g_hpart + (g*BCV + bc)*HWV;
    #pragma unroll
    for (int i = tid; i < HWV; i += NT) dst[i] = hs[i];
}

// ---------------- K2: sum NG partials + 2x2 block max pool (coalesced) ------
__global__ __launch_bounds__(1024) void pool2x2(float* __restrict__ out) {
    const int bc = blockIdx.x;
    const int t  = threadIdx.x;          // 1024 threads = 32x32 outputs
    const int oh = t >> 5;
    const int ow = t & 31;

    float best = 0.0f;                   // h >= 0 always (matches reference)
    #pragma unroll
    for (int dy = 0; dy < 2; dy++) {
        #pragma unroll
        for (int dx = 0; dx < 2; dx++) {
            const int p = (2*oh + dy)*WW + (2*ow + dx);
            float s = 0.0f;
            #pragma unroll
            for (int g = 0; g < NG; g++)
                s += g_hpart[(g*BCV + bc)*HWV + p];
            best = fmaxf(best, s);
        }
    }
    out[bc*(OHH*OWW) + t] = best;
}

// ---------------- launch -----------------------------------------------------
extern "C" void kernel_launch(void* const* d_in, const int* in_sizes, int n_in,
                              void* d_out, int out_size) {
    const float* u   = (const float*)d_in[0];   // (4,32,64,64)
    const float* rfs = (const float*)d_in[1];   // (64,64,64)
    float* out = (float*)d_out;                 // (4,32,32,32)

    build_k_lists<<<KK, 256>>>(rfs);
    rf_fused     <<<dim3(BCV, NG), NT>>>(u);
    pool2x2      <<<BCV, 1024>>>(out);
}

// round 3
// speedup vs baseline: 2.0450x; 1.0077x over previous
#include <cuda_runtime.h>

// Problem constants (fixed by the reference)
#define BB   4
#define CC   32
#define HH   64
#define WW   64
#define KK   64
#define HWV  (HH*WW)      // 4096
#define BCV  (BB*CC)      // 128
#define CAP  1024         // max support pixels per RF (analysis: <= ~960)
#define NG   4            // k-groups (partial-h accumulators)
#define NT   512          // threads per fused block
#define OHH  32
#define OWW  32

// ---------------- static device scratch (no allocation allowed) -------------
__device__ int   g_cnt[KK];          // support size per k
__device__ int2  g_pk[KK*CAP];       // packed {pixel, bits(rf * log2(e))}
__device__ float g_hpart[NG*BCV*HWV];// partial h sums per k-group (8 MB)

__device__ __forceinline__ float ex2_fast(float y) {
    float r;
    asm("ex2.approx.f32 %0, %1;" : "=f"(r) : "f"(y));
    return r;
}

// ---------------- P1: per-k compact support lists (parallel, deterministic) --
// One block of 1024 threads per k; 4 chunks of 1024 pixels.
// In-chunk position: warp ballot prefix + warp0 shfl-scan of 32 warp counts.
__global__ __launch_bounds__(1024) void build_k_lists(const float* __restrict__ rfs) {
    const int k    = blockIdx.x;
    const int tid  = threadIdx.x;
    const int lane = tid & 31;
    const int wid  = tid >> 5;

    __shared__ int wcnt[32];   // per-warp active count
    __shared__ int woff[32];   // exclusive prefix of wcnt
    __shared__ int stotal;     // chunk total

    const float LOG2E = 1.4426950408889634f;
    int base = 0;

    #pragma unroll
    for (int c = 0; c < 4; c++) {
        const int p  = c*1024 + tid;
        const float rf = rfs[k*HWV + p];
        const bool act = (rf != 0.0f);
        const unsigned bal = __ballot_sync(0xffffffffu, act);
        if (lane == 0) wcnt[wid] = __popc(bal);
        __syncthreads();
        if (wid == 0) {
            int v = wcnt[lane];           // 32 warp counts
            int s = v;                    // inclusive scan via shfl
            #pragma unroll
            for (int o = 1; o < 32; o <<= 1) {
                int t = __shfl_up_sync(0xffffffffu, s, o);
                if (lane >= o) s += t;
            }
            woff[lane] = s - v;           // exclusive
            if (lane == 31) stotal = s;
        }
        __syncthreads();
        if (act) {
            const int pos = base + woff[wid] + __popc(bal & ((1u << lane) - 1u));
            if (pos < CAP) {
                int2 v;
                v.x = p;
                v.y = __float_as_int(rf * LOG2E);
                g_pk[k*CAP + pos] = v;
            }
        }
        base += stotal;                   // read after barrier; safe vs next write
    }
    if (tid == 0) g_cnt[k] = (base < CAP) ? base : CAP;
}

// ---------------- K1: fused masked softmax + h accumulation (pipelined) -----
// exp(v - m) / (exp(-m) + sum exp(v - m)) == exp(v) / (1 + sum exp(v))
// Next k's exponentials are computed inside the sync1..sync2 window of the
// current k's reduction, hiding LDG + MUFU latency. Smem RMWs for k and k+1
// are separated by two barriers -> race-free, deterministic.
__global__ __launch_bounds__(NT) void rf_fused(const float* __restrict__ u) {
    const int bc  = blockIdx.x;
    const int g   = blockIdx.y;
    const int tid = threadIdx.x;

    __shared__ float us[HWV];   // input tile (16 KB)
    __shared__ float hs[HWV];   // partial h accumulator (16 KB)
    __shared__ float wred[16];
    __shared__ float sinv;

    const float* __restrict__ up = u + bc*HWV;
    #pragma unroll
    for (int i = tid; i < HWV; i += NT) { us[i] = up[i]; hs[i] = 0.0f; }
    __syncthreads();

    // strided k assignment: group g handles k = g, g+NG, ...
    // Each thread owns list elements 2*tid and 2*tid+1 (one LDG.128).
    const int i0 = 2*tid, i1 = 2*tid + 1;

    // prologue: compute e for first k
    int   p0 = 0, p1 = 0;
    float e0 = 0.0f, e1 = 0.0f;
    {
        const int k = g;
        const int n = g_cnt[k];
        const int4 v = ((const int4*)(g_pk + k*CAP))[tid];
        if (i0 < n) { p0 = v.x; e0 = ex2_fast(us[p0] * __int_as_float(v.y)); }
        if (i1 < n) { p1 = v.z; e1 = ex2_fast(us[p1] * __int_as_float(v.w)); }
    }

    for (int kk = 0; kk < KK/NG; kk++) {
        // ---- reduce current k's sum ----
        float lsum = e0 + e1;
        #pragma unroll
        for (int o = 16; o > 0; o >>= 1) lsum += __shfl_down_sync(0xffffffffu, lsum, o);
        if ((tid & 31) == 0) wred[tid >> 5] = lsum;
        __syncthreads();                              // sync1
        if (tid < 32) {
            float s = (tid < 16) ? wred[tid] : 0.0f;
            #pragma unroll
            for (int o = 8; o > 0; o >>= 1) s += __shfl_down_sync(0xffffffffu, s, o);
            if (tid == 0) sinv = 1.0f / (1.0f + s);
        }

        // ---- overlap: compute NEXT k's exponentials ----
        int   q0 = 0, q1 = 0;
        float f0 = 0.0f, f1 = 0.0f;
        if (kk + 1 < KK/NG) {
            const int kn = g + (kk + 1)*NG;
            const int n  = g_cnt[kn];
            const int4 v = ((const int4*)(g_pk + kn*CAP))[tid];
            if (i0 < n) { q0 = v.x; f0 = ex2_fast(us[q0] * __int_as_float(v.y)); }
            if (i1 < n) { q1 = v.z; f1 = ex2_fast(us[q1] * __int_as_float(v.w)); }
        }
        __syncthreads();                              // sync2
        const float inv = sinv;

        // ---- scatter current k (race-free: pixels distinct within k) ----
        if (e0 != 0.0f) hs[p0] += e0 * inv;
        if (e1 != 0.0f) hs[p1] += e1 * inv;

        p0 = q0; p1 = q1; e0 = f0; e1 = f1;
    }
    __syncthreads();

    float* __restrict__ dst = g_hpart + (g*BCV + bc)*HWV;
    #pragma unroll
    for (int i = tid; i < HWV; i += NT) dst[i] = hs[i];
}

// ---------------- K2: sum NG partials + 2x2 block max pool (coalesced) ------
__global__ __launch_bounds__(1024) void pool2x2(float* __restrict__ out) {
    const int bc = blockIdx.x;
    const int t  = threadIdx.x;          // 1024 threads = 32x32 outputs
    const int oh = t >> 5;
    const int ow = t & 31;

    float best = 0.0f;                   // h >= 0 always (matches reference)
    #pragma unroll
    for (int dy = 0; dy < 2; dy++) {
        #pragma unroll
        for (int dx = 0; dx < 2; dx++) {
            const int p = (2*oh + dy)*WW + (2*ow + dx);
            float s = 0.0f;
            #pragma unroll
            for (int g = 0; g < NG; g++)
                s += g_hpart[(g*BCV + bc)*HWV + p];
            best = fmaxf(best, s);
        }
    }
    out[bc*(OHH*OWW) + t] = best;
}

// ---------------- launch -----------------------------------------------------
extern "C" void kernel_launch(void* const* d_in, const int* in_sizes, int n_in,
                              void* d_out, int out_size) {
    const float* u   = (const float*)d_in[0];   // (4,32,64,64)
    const float* rfs = (const float*)d_in[1];   // (64,64,64)
    float* out = (float*)d_out;                 // (4,32,32,32)

    build_k_lists<<<KK, 1024>>>(rfs);
    rf_fused     <<<dim3(BCV, NG), NT>>>(u);
    pool2x2      <<<BCV, 1024>>>(out);
}